// round 12
// baseline (speedup 1.0000x reference)
#include <cuda_runtime.h>
#include <cuda_bf16.h>
#include <mma.h>
#include <math.h>
#include <cstdint>

using namespace nvcuda;

// ---------------- problem constants ----------------
constexpr int B_   = 4;
constexpr int S_   = 4096;
constexpr int D_   = 1024;   // token dim
constexpr int H_   = 1024;   // hidden dim
constexpr int WIN  = 256;
constexpr int STRIDE_ = 128;
constexpr int GLOB = 16;
constexpr float EPS = 1e-5f;
constexpr float SCALE = 1.0f / 32.0f;  // 1/sqrt(1024)

constexpr int ROWS = B_ * S_;          // 16384
constexpr size_t NELEM = (size_t)ROWS * D_;  // 16,777,216

// ---------------- scratch (static device globals; allocation-free) ----------
__device__ __nv_bfloat16 g_x[NELEM];       // LN1 output (bf16)
__device__ __nv_bfloat16 g_wq[D_ * H_];
__device__ __nv_bfloat16 g_wk[D_ * H_];
__device__ __nv_bfloat16 g_wv[D_ * D_];
__device__ __nv_bfloat16 g_wo[D_ * D_];
__device__ __nv_bfloat16 g_Q[NELEM];
__device__ __nv_bfloat16 g_K[NELEM];
__device__ __nv_bfloat16 g_V[NELEM];
__device__ __nv_bfloat16 g_attn[NELEM];    // attention output (bf16)
__device__ __nv_bfloat16 g_o[NELEM];       // attn @ Wo (bf16)

// ---------------- cp.async helpers ----------------
__device__ __forceinline__ void cp16(void* sdst, const void* gsrc) {
    unsigned sa = (unsigned)__cvta_generic_to_shared(sdst);
    asm volatile("cp.async.cg.shared.global [%0], [%1], 16;\n" :: "r"(sa), "l"(gsrc));
}
#define CP_COMMIT() asm volatile("cp.async.commit_group;\n" ::: "memory")
#define CP_WAIT1()  asm volatile("cp.async.wait_group 1;\n" ::: "memory")

// ---------------- weight conversion (all 4 weights, 1 launch) --------------
__global__ void cvt4_kernel(const float* __restrict__ w0, const float* __restrict__ w1,
                            const float* __restrict__ w2, const float* __restrict__ w3,
                            __nv_bfloat16* __restrict__ o0, __nv_bfloat16* __restrict__ o1,
                            __nv_bfloat16* __restrict__ o2, __nv_bfloat16* __restrict__ o3) {
    const float* w = (blockIdx.y == 0) ? w0 : (blockIdx.y == 1) ? w1 : (blockIdx.y == 2) ? w2 : w3;
    __nv_bfloat16* o = (blockIdx.y == 0) ? o0 : (blockIdx.y == 1) ? o1 : (blockIdx.y == 2) ? o2 : o3;
    int i = blockIdx.x * blockDim.x + threadIdx.x;
    if (i < D_ * H_) o[i] = __float2bfloat16(w[i]);
}

// ---------------- LayerNorm 1: tokens -> bf16 x ----------------
__global__ void ln1_kernel(const float* __restrict__ tokens,
                           const float* __restrict__ g, const float* __restrict__ beta,
                           __nv_bfloat16* __restrict__ out) {
    int row = blockIdx.x;
    int tid = threadIdx.x;
    const float* r = tokens + (size_t)row * D_;
    float v[4], s = 0.f, ss = 0.f;
#pragma unroll
    for (int c = 0; c < 4; c++) {
        v[c] = r[tid + 256 * c];
        s += v[c]; ss += v[c] * v[c];
    }
    __shared__ float rs[256], rss[256];
    rs[tid] = s; rss[tid] = ss;
    __syncthreads();
    for (int o = 128; o > 0; o >>= 1) {
        if (tid < o) { rs[tid] += rs[tid + o]; rss[tid] += rss[tid + o]; }
        __syncthreads();
    }
    float mean = rs[0] * (1.0f / D_);
    float var  = rss[0] * (1.0f / D_) - mean * mean;
    float inv  = rsqrtf(var + EPS);
#pragma unroll
    for (int c = 0; c < 4; c++) {
        int idx = tid + 256 * c;
        out[(size_t)row * D_ + idx] =
            __float2bfloat16((v[c] - mean) * inv * g[idx] + beta[idx]);
    }
}

// ---------------- LayerNorm 2: tokens + 0.1*o(bf16) -> fp32 out ------------
__global__ void ln2_kernel(const float* __restrict__ tokens,
                           const __nv_bfloat16* __restrict__ oin,
                           const float* __restrict__ g, const float* __restrict__ beta,
                           float* __restrict__ out) {
    int row = blockIdx.x;
    int tid = threadIdx.x;
    const float* r  = tokens + (size_t)row * D_;
    const __nv_bfloat16* ro = oin + (size_t)row * D_;
    float v[4], s = 0.f, ss = 0.f;
#pragma unroll
    for (int c = 0; c < 4; c++) {
        int idx = tid + 256 * c;
        v[c] = r[idx] + 0.1f * __bfloat162float(ro[idx]);
        s += v[c]; ss += v[c] * v[c];
    }
    __shared__ float rs[256], rss[256];
    rs[tid] = s; rss[tid] = ss;
    __syncthreads();
    for (int o = 128; o > 0; o >>= 1) {
        if (tid < o) { rs[tid] += rs[tid + o]; rss[tid] += rss[tid + o]; }
        __syncthreads();
    }
    float mean = rs[0] * (1.0f / D_);
    float var  = rss[0] * (1.0f / D_) - mean * mean;
    float inv  = rsqrtf(var + EPS);
#pragma unroll
    for (int c = 0; c < 4; c++) {
        int idx = tid + 256 * c;
        out[(size_t)row * D_ + idx] = (v[c] - mean) * inv * g[idx] + beta[idx];
    }
}

// ---------------- wmma bf16 GEMM v2: 128x256x64 tiles, 512 threads ---------
// C[M,1024] = A[M,1024] * B[1024,1024]; blockIdx.z selects (B,C) pair.
// 16 warps in 4x4 grid, warp tile 32x64 (2x4 accum frags). cp.async
// double-buffered BK=64 slabs: 32 wmma/warp between barrier pairs.
constexpr int GBM = 128, GBN = 256, GBK = 64;
constexpr int ALD = 80;              // A smem ld (64 + 16 pad)
constexpr int BLD = 264;             // B smem ld (256 + 8 pad)
constexpr int GTHREADS = 512;
constexpr int ABUF = GBM * ALD;      // elems per A buffer (10240)
constexpr int BBUF = GBK * BLD;      // elems per B buffer (16896)
constexpr size_t GEMM_SMEM = (size_t)(2 * ABUF + 2 * BBUF) * 2;  // 108544 B
constexpr int GNKC = D_ / GBK;       // 16 k-chunks

template <typename OT>
__global__ __launch_bounds__(GTHREADS, 1)
void gemm_kernel(const __nv_bfloat16* __restrict__ A,
                 const __nv_bfloat16* __restrict__ B0,
                 const __nv_bfloat16* __restrict__ B1,
                 const __nv_bfloat16* __restrict__ B2,
                 OT* __restrict__ C0, OT* __restrict__ C1, OT* __restrict__ C2) {
    const __nv_bfloat16* Bm = (blockIdx.z == 0) ? B0 : (blockIdx.z == 1) ? B1 : B2;
    OT* C = (blockIdx.z == 0) ? C0 : (blockIdx.z == 1) ? C1 : C2;

    extern __shared__ __align__(16) __nv_bfloat16 gsm[];
    __nv_bfloat16* As = gsm;                 // [2][GBM][ALD]
    __nv_bfloat16* Bs = gsm + 2 * ABUF;      // [2][GBK][BLD]

    int m0 = blockIdx.y * GBM;
    int n0 = blockIdx.x * GBN;
    int tid = threadIdx.x;
    int lane = tid & 31;
    int wid = tid >> 5;
    int wm = wid & 3;          // row group (32 rows each)
    int wn = wid >> 2;         // col group (64 cols each)

    wmma::fragment<wmma::accumulator, 16, 16, 16, float> cf[2][4];
#pragma unroll
    for (int r = 0; r < 2; r++)
#pragma unroll
        for (int c = 0; c < 4; c++)
            wmma::fill_fragment(cf[r][c], 0.0f);

    auto issue = [&](int s, int k0) {
        __nv_bfloat16* Ab = As + s * ABUF;
        __nv_bfloat16* Bb = Bs + s * BBUF;
#pragma unroll
        for (int it = 0; it < 2; it++) {     // A: 128x64 = 1024 uint4
            int idx = tid + it * GTHREADS;
            int row = idx >> 3, c8 = idx & 7;
            cp16(&Ab[row * ALD + c8 * 8],
                 &A[(size_t)(m0 + row) * 1024 + k0 + c8 * 8]);
        }
#pragma unroll
        for (int it = 0; it < 4; it++) {     // B: 64x256 = 2048 uint4
            int idx = tid + it * GTHREADS;
            int row = idx >> 5, c32 = idx & 31;
            cp16(&Bb[row * BLD + c32 * 8],
                 &Bm[(size_t)(k0 + row) * 1024 + n0 + c32 * 8]);
        }
    };

    issue(0, 0);
    CP_COMMIT();

    for (int kt = 0; kt < GNKC; kt++) {
        if (kt + 1 < GNKC) issue((kt + 1) & 1, (kt + 1) * GBK);
        CP_COMMIT();           // empty group at tail keeps wait_group 1 correct
        CP_WAIT1();
        __syncthreads();
        int s = kt & 1;
        __nv_bfloat16* Ab = As + s * ABUF;
        __nv_bfloat16* Bb = Bs + s * BBUF;
#pragma unroll
        for (int kk = 0; kk < 4; kk++) {
            wmma::fragment<wmma::matrix_a, 16, 16, 16, __nv_bfloat16, wmma::row_major> af[2];
            wmma::fragment<wmma::matrix_b, 16, 16, 16, __nv_bfloat16, wmma::row_major> bf[4];
#pragma unroll
            for (int r = 0; r < 2; r++)
                wmma::load_matrix_sync(af[r], Ab + (wm * 32 + r * 16) * ALD + kk * 16, ALD);
#pragma unroll
            for (int c = 0; c < 4; c++)
                wmma::load_matrix_sync(bf[c], Bb + (kk * 16) * BLD + wn * 64 + c * 16, BLD);
#pragma unroll
            for (int r = 0; r < 2; r++)
#pragma unroll
                for (int c = 0; c < 4; c++)
                    wmma::mma_sync(cf[r][c], af[r], bf[c], cf[r][c]);
        }
        __syncthreads();
    }

    // ---- epilogue ----
    if constexpr (sizeof(OT) == 4) {
#pragma unroll
        for (int r = 0; r < 2; r++)
#pragma unroll
            for (int c = 0; c < 4; c++) {
                float* p = (float*)C + (size_t)(m0 + wm * 32 + r * 16) * 1024
                           + n0 + wn * 64 + c * 16;
                wmma::store_matrix_sync(p, cf[r][c], 1024, wmma::mem_row_major);
            }
    } else {
        // bf16: stage per-warp 16x16 fp32 tile in smem, convert, 16B stores
        __syncthreads();
        float* my = (float*)gsm + wid * 256;
#pragma unroll
        for (int r = 0; r < 2; r++)
#pragma unroll
            for (int c = 0; c < 4; c++) {
                wmma::store_matrix_sync(my, cf[r][c], 16, wmma::mem_row_major);
                __syncwarp();
                int r2 = lane >> 1;
                int cb = (lane & 1) * 8;
                __nv_bfloat16 pk[8];
#pragma unroll
                for (int e = 0; e < 8; e++)
                    pk[e] = __float2bfloat16(my[r2 * 16 + cb + e]);
                __nv_bfloat16* p = (__nv_bfloat16*)C
                    + (size_t)(m0 + wm * 32 + r * 16 + r2) * 1024
                    + n0 + wn * 64 + c * 16 + cb;
                *(uint4*)p = *(uint4*)pk;
                __syncwarp();
            }
    }
}

// ---------------- sparse attention v3: warp-autonomous pipelines -----------
constexpr int QT = 16;
constexpr int MAXU = 800;
constexpr int ATHREADS = 512;
constexpr int LDQ  = 1032;
constexpr int LDK  = 72;
constexpr int LDSC = 800;
constexpr int LDW  = 808;
constexpr int WBUF = 16 * LDK;

constexpr size_t ATTN_SMEM =
    (size_t)QT * LDQ * 2
  + (size_t)16 * 2 * WBUF * 2
  + (size_t)QT * LDW * 2
  + (size_t)QT * LDSC * 4
  + (size_t)MAXU * 4 + 16;

__global__ __launch_bounds__(ATHREADS, 1)
void attn_kernel(const __nv_bfloat16* __restrict__ Q,
                 const __nv_bfloat16* __restrict__ K,
                 const __nv_bfloat16* __restrict__ V,
                 __nv_bfloat16* __restrict__ attn) {
    extern __shared__ char smem_raw[];
    __nv_bfloat16* Qs  = (__nv_bfloat16*)smem_raw;
    __nv_bfloat16* Kb  = Qs + QT * LDQ;
    __nv_bfloat16* scb = Kb + 16 * 2 * WBUF;
    float*         sc  = (float*)(scb + QT * LDW);
    int*         klist = (int*)(sc + QT * LDSC);
    int*          cntp = klist + MAXU;

    int b    = blockIdx.y;
    int i0   = (gridDim.x - 1 - blockIdx.x) * QT;
    int tid  = threadIdx.x;
    int lane = tid & 31;
    int wid  = tid >> 5;

    const __nv_bfloat16* Qbase = Q + ((size_t)b * S_ + i0) * H_;
#pragma unroll
    for (int it = 0; it < 4; it++) {
        int id = tid + it * ATHREADS;
        int row = id >> 7, seg = id & 127;
        *(uint4*)&Qs[row * LDQ + seg * 8] = *(const uint4*)&Qbase[row * 1024 + seg * 8];
    }

    int imax   = i0 + QT - 1;
    int wstart = max(0, i0 - (WIN - 1));
    if (wid == 0) {
        int c = 0;
        for (int j0 = 0; j0 <= imax; j0 += 32) {
            int j = j0 + lane;
            int u = ((j - i0) % STRIDE_ + STRIDE_) % STRIDE_;
            bool inc = (j <= imax) && ((j >= wstart) || (j < GLOB) || (u < QT));
            unsigned msk = __ballot_sync(0xffffffffu, inc);
            if (inc) klist[c + __popc(msk & ((1u << lane) - 1u))] = j;
            c += __popc(msk);
        }
        if (lane == 0) *cntp = c;
        for (int k = c + lane; k < MAXU; k += 32) klist[k] = 0;
    }
    __syncthreads();                                   // barrier #1
    int cnt = *cntp;
    int ntiles = (cnt + 15) >> 4;

    __nv_bfloat16* Kw = Kb + wid * 2 * WBUF;
    const __nv_bfloat16* Kbase = K + (size_t)b * S_ * H_;
    const __nv_bfloat16* Vbase = V + (size_t)b * S_ * H_;

    {
        int nmy = 0;
        for (int kt = wid; kt < ntiles; kt += 16) nmy++;
        int tslabs = nmy * 16;

        auto issueK = [&](int it) {
            int buf = it & 1;
            int kt  = wid + ((it >> 4) << 4);
            int k0  = (it & 15) * 64;
#pragma unroll
            for (int l = 0; l < 4; l++) {
                int id = lane + 32 * l;
                int row = id >> 3, seg = id & 7;
                int j = klist[kt * 16 + row];
                cp16(&Kw[buf * WBUF + row * LDK + seg * 8],
                     Kbase + (size_t)j * 1024 + k0 + seg * 8);
            }
        };

        wmma::fragment<wmma::accumulator, 16, 16, 16, float> sf;
        wmma::fill_fragment(sf, 0.0f);
        if (tslabs > 0) { issueK(0); }
        CP_COMMIT();
        for (int it = 0; it < tslabs; it++) {
            if (it + 1 < tslabs) issueK(it + 1);
            CP_COMMIT();
            CP_WAIT1();
            __syncwarp();
            int buf = it & 1;
            int k0  = (it & 15) * 64;
#pragma unroll
            for (int i = 0; i < 4; i++) {
                wmma::fragment<wmma::matrix_a, 16, 16, 16, __nv_bfloat16, wmma::row_major> af;
                wmma::fragment<wmma::matrix_b, 16, 16, 16, __nv_bfloat16, wmma::col_major> bf;
                wmma::load_matrix_sync(af, Qs + k0 + i * 16, LDQ);
                wmma::load_matrix_sync(bf, Kw + buf * WBUF + i * 16, LDK);
                wmma::mma_sync(sf, af, bf, sf);
            }
            if ((it & 15) == 15) {
                int kt = wid + ((it >> 4) << 4);
                wmma::store_matrix_sync(sc + kt * 16, sf, LDSC, wmma::mem_row_major);
                wmma::fill_fragment(sf, 0.0f);
            }
        }
    }
    __syncthreads();                                   // barrier #2

    int cnt16 = ntiles << 4;
    {
        int q = wid;
        int i = i0 + q;
        float m = -INFINITY;
        for (int ku = lane; ku < cnt; ku += 32) {
            int j = klist[ku];
            int d = i - j;
            bool ok = (d >= 0) && ((d < WIN) || ((d & (STRIDE_ - 1)) == 0) || (j < GLOB));
            float v = ok ? sc[q * LDSC + ku] * SCALE : -INFINITY;
            sc[q * LDSC + ku] = v;
            m = fmaxf(m, v);
        }
#pragma unroll
        for (int o = 16; o > 0; o >>= 1) m = fmaxf(m, __shfl_xor_sync(0xffffffffu, m, o));
        float ssum = 0.f;
        for (int ku = lane; ku < cnt; ku += 32) {
            float e = __expf(sc[q * LDSC + ku] - m);
            sc[q * LDSC + ku] = e;
            ssum += e;
        }
#pragma unroll
        for (int o = 16; o > 0; o >>= 1) ssum += __shfl_xor_sync(0xffffffffu, ssum, o);
        float inv = 1.f / ssum;
        for (int ku = lane; ku < cnt16; ku += 32) {
            float w = (ku < cnt) ? sc[q * LDSC + ku] * inv : 0.f;
            scb[q * LDW + ku] = __float2bfloat16(w);
        }
    }
    __syncthreads();                                   // barrier #3

    int d0 = wid * 64;
    {
        auto issueV = [&](int c) {
            int buf = c & 1;
#pragma unroll
            for (int l = 0; l < 4; l++) {
                int id = lane + 32 * l;
                int row = id >> 3, seg = id & 7;
                int j = klist[c * 16 + row];
                cp16(&Kw[buf * WBUF + row * LDK + seg * 8],
                     Vbase + (size_t)j * 1024 + d0 + seg * 8);
            }
        };

        wmma::fragment<wmma::accumulator, 16, 16, 16, float> of[4];
#pragma unroll
        for (int i = 0; i < 4; i++) wmma::fill_fragment(of[i], 0.0f);

        issueV(0);
        CP_COMMIT();
        for (int c = 0; c < ntiles; c++) {
            if (c + 1 < ntiles) issueV(c + 1);
            CP_COMMIT();
            CP_WAIT1();
            __syncwarp();
            int buf = c & 1;
            wmma::fragment<wmma::matrix_a, 16, 16, 16, __nv_bfloat16, wmma::row_major> af;
            wmma::load_matrix_sync(af, scb + c * 16, LDW);
#pragma unroll
            for (int i = 0; i < 4; i++) {
                wmma::fragment<wmma::matrix_b, 16, 16, 16, __nv_bfloat16, wmma::row_major> bf;
                wmma::load_matrix_sync(bf, Kw + buf * WBUF + i * 16, LDK);
                wmma::mma_sync(of[i], af, bf, of[i]);
            }
        }

        float* my = sc + wid * 256;
#pragma unroll
        for (int i = 0; i < 4; i++) {
            wmma::store_matrix_sync(my, of[i], 16, wmma::mem_row_major);
            __syncwarp();
            int r2 = lane >> 1, cb = (lane & 1) * 8;
            __nv_bfloat16 pk[8];
#pragma unroll
            for (int e = 0; e < 8; e++) pk[e] = __float2bfloat16(my[r2 * 16 + cb + e]);
            *(uint4*)(attn + ((size_t)b * S_ + i0 + r2) * 1024 + d0 + i * 16 + cb) = *(uint4*)pk;
            __syncwarp();
        }
    }
}

// ---------------- launch ----------------
extern "C" void kernel_launch(void* const* d_in, const int* in_sizes, int n_in,
                              void* d_out, int out_size) {
    const float* tokens = (const float*)d_in[0];
    const float* Wq = (const float*)d_in[1];
    const float* Wk = (const float*)d_in[2];
    const float* Wv = (const float*)d_in[3];
    const float* Wo = (const float*)d_in[4];
    const float* g1 = (const float*)d_in[5];
    const float* b1 = (const float*)d_in[6];
    const float* g2 = (const float*)d_in[7];
    const float* b2 = (const float*)d_in[8];
    float* out = (float*)d_out;

    __nv_bfloat16 *x, *wq, *wk, *wv, *wo, *Qb, *Kb, *Vb, *attn, *ob;
    cudaGetSymbolAddress((void**)&x,    g_x);
    cudaGetSymbolAddress((void**)&wq,   g_wq);
    cudaGetSymbolAddress((void**)&wk,   g_wk);
    cudaGetSymbolAddress((void**)&wv,   g_wv);
    cudaGetSymbolAddress((void**)&wo,   g_wo);
    cudaGetSymbolAddress((void**)&Qb,   g_Q);
    cudaGetSymbolAddress((void**)&Kb,   g_K);
    cudaGetSymbolAddress((void**)&Vb,   g_V);
    cudaGetSymbolAddress((void**)&attn, g_attn);
    cudaGetSymbolAddress((void**)&ob,   g_o);

    cvt4_kernel<<<dim3((D_ * H_ + 255) / 256, 4), 256>>>(Wq, Wk, Wv, Wo, wq, wk, wv, wo);

    ln1_kernel<<<ROWS, 256>>>(tokens, g1, b1, x);

    // fused QKV projection -> bf16 (wmma v2)
    cudaFuncSetAttribute(gemm_kernel<__nv_bfloat16>,
                         cudaFuncAttributeMaxDynamicSharedMemorySize, (int)GEMM_SMEM);
    gemm_kernel<__nv_bfloat16><<<dim3(H_ / GBN, ROWS / GBM, 3), GTHREADS, GEMM_SMEM>>>(
        x, wq, wk, wv, Qb, Kb, Vb);

    // sparse attention (warp-autonomous tensor-core)
    cudaFuncSetAttribute(attn_kernel, cudaFuncAttributeMaxDynamicSharedMemorySize,
                         (int)ATTN_SMEM);
    attn_kernel<<<dim3(S_ / QT, B_), ATHREADS, ATTN_SMEM>>>(Qb, Kb, Vb, attn);

    // output projection -> bf16 (wmma v2)
    gemm_kernel<__nv_bfloat16><<<dim3(D_ / GBN, ROWS / GBM, 1), GTHREADS, GEMM_SMEM>>>(
        attn, wo, wo, wo, ob, ob, ob);

    // residual + LN2
    ln2_kernel<<<ROWS, 256>>>(tokens, ob, g2, b2, out);
}

// round 15
// speedup vs baseline: 1.0531x; 1.0531x over previous
#include <cuda_runtime.h>
#include <cuda_bf16.h>
#include <mma.h>
#include <math.h>
#include <cstdint>

using namespace nvcuda;

// ---------------- problem constants ----------------
constexpr int B_   = 4;
constexpr int S_   = 4096;
constexpr int D_   = 1024;   // token dim
constexpr int H_   = 1024;   // hidden dim
constexpr int WIN  = 256;
constexpr int STRIDE_ = 128;
constexpr int GLOB = 16;
constexpr float EPS = 1e-5f;
constexpr float SCALE = 1.0f / 32.0f;  // 1/sqrt(1024)

constexpr int ROWS = B_ * S_;          // 16384
constexpr size_t NELEM = (size_t)ROWS * D_;  // 16,777,216

// ---------------- scratch (static device globals; allocation-free) ----------
__device__ __nv_bfloat16 g_x[NELEM];       // LN1 output (bf16)
__device__ __nv_bfloat16 g_wq[D_ * H_];
__device__ __nv_bfloat16 g_wk[D_ * H_];
__device__ __nv_bfloat16 g_wv[D_ * D_];
__device__ __nv_bfloat16 g_wo[D_ * D_];
__device__ __nv_bfloat16 g_Q[NELEM];
__device__ __nv_bfloat16 g_K[NELEM];
__device__ __nv_bfloat16 g_V[NELEM];
__device__ __nv_bfloat16 g_attn[NELEM];    // attention output (bf16)
__device__ __nv_bfloat16 g_o[NELEM];       // attn @ Wo (bf16)

// ---------------- cp.async helpers ----------------
__device__ __forceinline__ void cp16(void* sdst, const void* gsrc) {
    unsigned sa = (unsigned)__cvta_generic_to_shared(sdst);
    asm volatile("cp.async.cg.shared.global [%0], [%1], 16;\n" :: "r"(sa), "l"(gsrc));
}
#define CP_COMMIT() asm volatile("cp.async.commit_group;\n" ::: "memory")
#define CP_WAIT1()  asm volatile("cp.async.wait_group 1;\n" ::: "memory")

// ---------------- weight conversion (all 4 weights, 1 launch) --------------
__global__ void cvt4_kernel(const float* __restrict__ w0, const float* __restrict__ w1,
                            const float* __restrict__ w2, const float* __restrict__ w3,
                            __nv_bfloat16* __restrict__ o0, __nv_bfloat16* __restrict__ o1,
                            __nv_bfloat16* __restrict__ o2, __nv_bfloat16* __restrict__ o3) {
    const float* w = (blockIdx.y == 0) ? w0 : (blockIdx.y == 1) ? w1 : (blockIdx.y == 2) ? w2 : w3;
    __nv_bfloat16* o = (blockIdx.y == 0) ? o0 : (blockIdx.y == 1) ? o1 : (blockIdx.y == 2) ? o2 : o3;
    int i = blockIdx.x * blockDim.x + threadIdx.x;
    if (i < D_ * H_) o[i] = __float2bfloat16(w[i]);
}

// ---------------- LayerNorm 1: tokens -> bf16 x ----------------
__global__ void ln1_kernel(const float* __restrict__ tokens,
                           const float* __restrict__ g, const float* __restrict__ beta,
                           __nv_bfloat16* __restrict__ out) {
    int row = blockIdx.x;
    int tid = threadIdx.x;
    const float* r = tokens + (size_t)row * D_;
    float v[4], s = 0.f, ss = 0.f;
#pragma unroll
    for (int c = 0; c < 4; c++) {
        v[c] = r[tid + 256 * c];
        s += v[c]; ss += v[c] * v[c];
    }
    __shared__ float rs[256], rss[256];
    rs[tid] = s; rss[tid] = ss;
    __syncthreads();
    for (int o = 128; o > 0; o >>= 1) {
        if (tid < o) { rs[tid] += rs[tid + o]; rss[tid] += rss[tid + o]; }
        __syncthreads();
    }
    float mean = rs[0] * (1.0f / D_);
    float var  = rss[0] * (1.0f / D_) - mean * mean;
    float inv  = rsqrtf(var + EPS);
#pragma unroll
    for (int c = 0; c < 4; c++) {
        int idx = tid + 256 * c;
        out[(size_t)row * D_ + idx] =
            __float2bfloat16((v[c] - mean) * inv * g[idx] + beta[idx]);
    }
}

// ---------------- LayerNorm 2: tokens + 0.1*o(bf16) -> fp32 out ------------
__global__ void ln2_kernel(const float* __restrict__ tokens,
                           const __nv_bfloat16* __restrict__ oin,
                           const float* __restrict__ g, const float* __restrict__ beta,
                           float* __restrict__ out) {
    int row = blockIdx.x;
    int tid = threadIdx.x;
    const float* r  = tokens + (size_t)row * D_;
    const __nv_bfloat16* ro = oin + (size_t)row * D_;
    float v[4], s = 0.f, ss = 0.f;
#pragma unroll
    for (int c = 0; c < 4; c++) {
        int idx = tid + 256 * c;
        v[c] = r[idx] + 0.1f * __bfloat162float(ro[idx]);
        s += v[c]; ss += v[c] * v[c];
    }
    __shared__ float rs[256], rss[256];
    rs[tid] = s; rss[tid] = ss;
    __syncthreads();
    for (int o = 128; o > 0; o >>= 1) {
        if (tid < o) { rs[tid] += rs[tid + o]; rss[tid] += rss[tid + o]; }
        __syncthreads();
    }
    float mean = rs[0] * (1.0f / D_);
    float var  = rss[0] * (1.0f / D_) - mean * mean;
    float inv  = rsqrtf(var + EPS);
#pragma unroll
    for (int c = 0; c < 4; c++) {
        int idx = tid + 256 * c;
        out[(size_t)row * D_ + idx] = (v[c] - mean) * inv * g[idx] + beta[idx];
    }
}

// ---------------- wmma bf16 GEMM v3: 128x128x64, 3-stage, 1 sync/iter ------
// C[M,1024] = A[M,1024] * B[1024,1024]; blockIdx.z selects (B,C) pair.
// 256 threads (8 warps, 4x2 grid), warp tile 32x64 (2x4 frags). 3-stage
// cp.async pipeline, CUTLASS multistage ordering: ONE __syncthreads per
// k-chunk. 106 KB smem -> 2 CTAs/SM overlap each other's barrier shadows.
constexpr int GBM = 128, GBN = 128, GBK = 64;
constexpr int ALD = 72;              // A smem ld (64 + 8 pad)
constexpr int BLD = 136;             // B smem ld (128 + 8 pad)
constexpr int GTHREADS = 256;
constexpr int GSTAGES = 3;
constexpr int ABUF = GBM * ALD;      // 9216 elems
constexpr int BBUF = GBK * BLD;      // 8704 elems
constexpr size_t GEMM_SMEM = (size_t)GSTAGES * (ABUF + BBUF) * 2;  // 107520 B
constexpr int GNKC = D_ / GBK;       // 16 k-chunks

template <typename OT>
__global__ __launch_bounds__(GTHREADS, 2)
void gemm_kernel(const __nv_bfloat16* __restrict__ A,
                 const __nv_bfloat16* __restrict__ B0,
                 const __nv_bfloat16* __restrict__ B1,
                 const __nv_bfloat16* __restrict__ B2,
                 OT* __restrict__ C0, OT* __restrict__ C1, OT* __restrict__ C2) {
    const __nv_bfloat16* Bm = (blockIdx.z == 0) ? B0 : (blockIdx.z == 1) ? B1 : B2;
    OT* C = (blockIdx.z == 0) ? C0 : (blockIdx.z == 1) ? C1 : C2;

    extern __shared__ __align__(16) __nv_bfloat16 gsm[];
    __nv_bfloat16* As = gsm;                        // [3][GBM][ALD]
    __nv_bfloat16* Bs = gsm + GSTAGES * ABUF;       // [3][GBK][BLD]

    int m0 = blockIdx.y * GBM;
    int n0 = blockIdx.x * GBN;
    int tid = threadIdx.x;
    int lane = tid & 31;
    int wid = tid >> 5;
    int wm = wid & 3;          // row group (32 rows each)
    int wn = wid >> 2;         // col group (64 cols each)

    wmma::fragment<wmma::accumulator, 16, 16, 16, float> cf[2][4];
#pragma unroll
    for (int r = 0; r < 2; r++)
#pragma unroll
        for (int c = 0; c < 4; c++)
            wmma::fill_fragment(cf[r][c], 0.0f);

    auto issue = [&](int s, int k0) {
        __nv_bfloat16* Ab = As + s * ABUF;
        __nv_bfloat16* Bb = Bs + s * BBUF;
#pragma unroll
        for (int it = 0; it < 4; it++) {     // A: 128x64 = 1024 uint4
            int idx = tid + it * GTHREADS;
            int row = idx >> 3, c8 = idx & 7;
            cp16(&Ab[row * ALD + c8 * 8],
                 &A[(size_t)(m0 + row) * 1024 + k0 + c8 * 8]);
        }
#pragma unroll
        for (int it = 0; it < 4; it++) {     // B: 64x128 = 1024 uint4
            int idx = tid + it * GTHREADS;
            int row = idx >> 4, c16 = idx & 15;
            cp16(&Bb[row * BLD + c16 * 8],
                 &Bm[(size_t)(k0 + row) * 1024 + n0 + c16 * 8]);
        }
    };

    // prologue: stages 0,1 in flight
    issue(0, 0);
    CP_COMMIT();
    issue(1, GBK);
    CP_COMMIT();

    for (int kt = 0; kt < GNKC; kt++) {
        CP_WAIT1();            // chunk kt ready (<=1 group outstanding)
        __syncthreads();       // all warps done with compute kt-1
        if (kt + 2 < GNKC) issue((kt + 2) % GSTAGES, (kt + 2) * GBK);
        CP_COMMIT();           // empty commit at tail keeps wait count valid

        int s = kt % GSTAGES;
        __nv_bfloat16* Ab = As + s * ABUF;
        __nv_bfloat16* Bb = Bs + s * BBUF;
#pragma unroll
        for (int kk = 0; kk < 4; kk++) {
            wmma::fragment<wmma::matrix_a, 16, 16, 16, __nv_bfloat16, wmma::row_major> af[2];
            wmma::fragment<wmma::matrix_b, 16, 16, 16, __nv_bfloat16, wmma::row_major> bf[4];
#pragma unroll
            for (int r = 0; r < 2; r++)
                wmma::load_matrix_sync(af[r], Ab + (wm * 32 + r * 16) * ALD + kk * 16, ALD);
#pragma unroll
            for (int c = 0; c < 4; c++)
                wmma::load_matrix_sync(bf[c], Bb + (kk * 16) * BLD + wn * 64 + c * 16, BLD);
#pragma unroll
            for (int r = 0; r < 2; r++)
#pragma unroll
                for (int c = 0; c < 4; c++)
                    wmma::mma_sync(cf[r][c], af[r], bf[c], cf[r][c]);
        }
    }
    __syncthreads();

    // ---- epilogue ----
    if constexpr (sizeof(OT) == 4) {
#pragma unroll
        for (int r = 0; r < 2; r++)
#pragma unroll
            for (int c = 0; c < 4; c++) {
                float* p = (float*)C + (size_t)(m0 + wm * 32 + r * 16) * 1024
                           + n0 + wn * 64 + c * 16;
                wmma::store_matrix_sync(p, cf[r][c], 1024, wmma::mem_row_major);
            }
    } else {
        // bf16: stage per-warp 16x16 fp32 tile in smem, convert, 16B stores
        float* my = (float*)gsm + wid * 256;
#pragma unroll
        for (int r = 0; r < 2; r++)
#pragma unroll
            for (int c = 0; c < 4; c++) {
                wmma::store_matrix_sync(my, cf[r][c], 16, wmma::mem_row_major);
                __syncwarp();
                int r2 = lane >> 1;
                int cb = (lane & 1) * 8;
                __nv_bfloat16 pk[8];
#pragma unroll
                for (int e = 0; e < 8; e++)
                    pk[e] = __float2bfloat16(my[r2 * 16 + cb + e]);
                __nv_bfloat16* p = (__nv_bfloat16*)C
                    + (size_t)(m0 + wm * 32 + r * 16 + r2) * 1024
                    + n0 + wn * 64 + c * 16 + cb;
                *(uint4*)p = *(uint4*)pk;
                __syncwarp();
            }
    }
}

// ---------------- sparse attention v3: warp-autonomous pipelines -----------
constexpr int QT = 16;
constexpr int MAXU = 800;
constexpr int ATHREADS = 512;
constexpr int LDQ  = 1032;
constexpr int LDK  = 72;
constexpr int LDSC = 800;
constexpr int LDW  = 808;
constexpr int WBUF = 16 * LDK;

constexpr size_t ATTN_SMEM =
    (size_t)QT * LDQ * 2
  + (size_t)16 * 2 * WBUF * 2
  + (size_t)QT * LDW * 2
  + (size_t)QT * LDSC * 4
  + (size_t)MAXU * 4 + 16;

__global__ __launch_bounds__(ATHREADS, 1)
void attn_kernel(const __nv_bfloat16* __restrict__ Q,
                 const __nv_bfloat16* __restrict__ K,
                 const __nv_bfloat16* __restrict__ V,
                 __nv_bfloat16* __restrict__ attn) {
    extern __shared__ char smem_raw[];
    __nv_bfloat16* Qs  = (__nv_bfloat16*)smem_raw;
    __nv_bfloat16* Kb  = Qs + QT * LDQ;
    __nv_bfloat16* scb = Kb + 16 * 2 * WBUF;
    float*         sc  = (float*)(scb + QT * LDW);
    int*         klist = (int*)(sc + QT * LDSC);
    int*          cntp = klist + MAXU;

    int b    = blockIdx.y;
    int i0   = (gridDim.x - 1 - blockIdx.x) * QT;
    int tid  = threadIdx.x;
    int lane = tid & 31;
    int wid  = tid >> 5;

    const __nv_bfloat16* Qbase = Q + ((size_t)b * S_ + i0) * H_;
#pragma unroll
    for (int it = 0; it < 4; it++) {
        int id = tid + it * ATHREADS;
        int row = id >> 7, seg = id & 127;
        *(uint4*)&Qs[row * LDQ + seg * 8] = *(const uint4*)&Qbase[row * 1024 + seg * 8];
    }

    int imax   = i0 + QT - 1;
    int wstart = max(0, i0 - (WIN - 1));
    if (wid == 0) {
        int c = 0;
        for (int j0 = 0; j0 <= imax; j0 += 32) {
            int j = j0 + lane;
            int u = ((j - i0) % STRIDE_ + STRIDE_) % STRIDE_;
            bool inc = (j <= imax) && ((j >= wstart) || (j < GLOB) || (u < QT));
            unsigned msk = __ballot_sync(0xffffffffu, inc);
            if (inc) klist[c + __popc(msk & ((1u << lane) - 1u))] = j;
            c += __popc(msk);
        }
        if (lane == 0) *cntp = c;
        for (int k = c + lane; k < MAXU; k += 32) klist[k] = 0;
    }
    __syncthreads();                                   // barrier #1
    int cnt = *cntp;
    int ntiles = (cnt + 15) >> 4;

    __nv_bfloat16* Kw = Kb + wid * 2 * WBUF;
    const __nv_bfloat16* Kbase = K + (size_t)b * S_ * H_;
    const __nv_bfloat16* Vbase = V + (size_t)b * S_ * H_;

    {
        int nmy = 0;
        for (int kt = wid; kt < ntiles; kt += 16) nmy++;
        int tslabs = nmy * 16;

        auto issueK = [&](int it) {
            int buf = it & 1;
            int kt  = wid + ((it >> 4) << 4);
            int k0  = (it & 15) * 64;
#pragma unroll
            for (int l = 0; l < 4; l++) {
                int id = lane + 32 * l;
                int row = id >> 3, seg = id & 7;
                int j = klist[kt * 16 + row];
                cp16(&Kw[buf * WBUF + row * LDK + seg * 8],
                     Kbase + (size_t)j * 1024 + k0 + seg * 8);
            }
        };

        wmma::fragment<wmma::accumulator, 16, 16, 16, float> sf;
        wmma::fill_fragment(sf, 0.0f);
        if (tslabs > 0) { issueK(0); }
        CP_COMMIT();
        for (int it = 0; it < tslabs; it++) {
            if (it + 1 < tslabs) issueK(it + 1);
            CP_COMMIT();
            CP_WAIT1();
            __syncwarp();
            int buf = it & 1;
            int k0  = (it & 15) * 64;
#pragma unroll
            for (int i = 0; i < 4; i++) {
                wmma::fragment<wmma::matrix_a, 16, 16, 16, __nv_bfloat16, wmma::row_major> af;
                wmma::fragment<wmma::matrix_b, 16, 16, 16, __nv_bfloat16, wmma::col_major> bf;
                wmma::load_matrix_sync(af, Qs + k0 + i * 16, LDQ);
                wmma::load_matrix_sync(bf, Kw + buf * WBUF + i * 16, LDK);
                wmma::mma_sync(sf, af, bf, sf);
            }
            if ((it & 15) == 15) {
                int kt = wid + ((it >> 4) << 4);
                wmma::store_matrix_sync(sc + kt * 16, sf, LDSC, wmma::mem_row_major);
                wmma::fill_fragment(sf, 0.0f);
            }
        }
    }
    __syncthreads();                                   // barrier #2

    int cnt16 = ntiles << 4;
    {
        int q = wid;
        int i = i0 + q;
        float m = -INFINITY;
        for (int ku = lane; ku < cnt; ku += 32) {
            int j = klist[ku];
            int d = i - j;
            bool ok = (d >= 0) && ((d < WIN) || ((d & (STRIDE_ - 1)) == 0) || (j < GLOB));
            float v = ok ? sc[q * LDSC + ku] * SCALE : -INFINITY;
            sc[q * LDSC + ku] = v;
            m = fmaxf(m, v);
        }
#pragma unroll
        for (int o = 16; o > 0; o >>= 1) m = fmaxf(m, __shfl_xor_sync(0xffffffffu, m, o));
        float ssum = 0.f;
        for (int ku = lane; ku < cnt; ku += 32) {
            float e = __expf(sc[q * LDSC + ku] - m);
            sc[q * LDSC + ku] = e;
            ssum += e;
        }
#pragma unroll
        for (int o = 16; o > 0; o >>= 1) ssum += __shfl_xor_sync(0xffffffffu, ssum, o);
        float inv = 1.f / ssum;
        for (int ku = lane; ku < cnt16; ku += 32) {
            float w = (ku < cnt) ? sc[q * LDSC + ku] * inv : 0.f;
            scb[q * LDW + ku] = __float2bfloat16(w);
        }
    }
    __syncthreads();                                   // barrier #3

    int d0 = wid * 64;
    {
        auto issueV = [&](int c) {
            int buf = c & 1;
#pragma unroll
            for (int l = 0; l < 4; l++) {
                int id = lane + 32 * l;
                int row = id >> 3, seg = id & 7;
                int j = klist[c * 16 + row];
                cp16(&Kw[buf * WBUF + row * LDK + seg * 8],
                     Vbase + (size_t)j * 1024 + d0 + seg * 8);
            }
        };

        wmma::fragment<wmma::accumulator, 16, 16, 16, float> of[4];
#pragma unroll
        for (int i = 0; i < 4; i++) wmma::fill_fragment(of[i], 0.0f);

        issueV(0);
        CP_COMMIT();
        for (int c = 0; c < ntiles; c++) {
            if (c + 1 < ntiles) issueV(c + 1);
            CP_COMMIT();
            CP_WAIT1();
            __syncwarp();
            int buf = c & 1;
            wmma::fragment<wmma::matrix_a, 16, 16, 16, __nv_bfloat16, wmma::row_major> af;
            wmma::load_matrix_sync(af, scb + c * 16, LDW);
#pragma unroll
            for (int i = 0; i < 4; i++) {
                wmma::fragment<wmma::matrix_b, 16, 16, 16, __nv_bfloat16, wmma::row_major> bf;
                wmma::load_matrix_sync(bf, Kw + buf * WBUF + i * 16, LDK);
                wmma::mma_sync(of[i], af, bf, of[i]);
            }
        }

        float* my = sc + wid * 256;
#pragma unroll
        for (int i = 0; i < 4; i++) {
            wmma::store_matrix_sync(my, of[i], 16, wmma::mem_row_major);
            __syncwarp();
            int r2 = lane >> 1, cb = (lane & 1) * 8;
            __nv_bfloat16 pk[8];
#pragma unroll
            for (int e = 0; e < 8; e++) pk[e] = __float2bfloat16(my[r2 * 16 + cb + e]);
            *(uint4*)(attn + ((size_t)b * S_ + i0 + r2) * 1024 + d0 + i * 16 + cb) = *(uint4*)pk;
            __syncwarp();
        }
    }
}

// ---------------- launch ----------------
extern "C" void kernel_launch(void* const* d_in, const int* in_sizes, int n_in,
                              void* d_out, int out_size) {
    const float* tokens = (const float*)d_in[0];
    const float* Wq = (const float*)d_in[1];
    const float* Wk = (const float*)d_in[2];
    const float* Wv = (const float*)d_in[3];
    const float* Wo = (const float*)d_in[4];
    const float* g1 = (const float*)d_in[5];
    const float* b1 = (const float*)d_in[6];
    const float* g2 = (const float*)d_in[7];
    const float* b2 = (const float*)d_in[8];
    float* out = (float*)d_out;

    __nv_bfloat16 *x, *wq, *wk, *wv, *wo, *Qb, *Kb, *Vb, *attn, *ob;
    cudaGetSymbolAddress((void**)&x,    g_x);
    cudaGetSymbolAddress((void**)&wq,   g_wq);
    cudaGetSymbolAddress((void**)&wk,   g_wk);
    cudaGetSymbolAddress((void**)&wv,   g_wv);
    cudaGetSymbolAddress((void**)&wo,   g_wo);
    cudaGetSymbolAddress((void**)&Qb,   g_Q);
    cudaGetSymbolAddress((void**)&Kb,   g_K);
    cudaGetSymbolAddress((void**)&Vb,   g_V);
    cudaGetSymbolAddress((void**)&attn, g_attn);
    cudaGetSymbolAddress((void**)&ob,   g_o);

    cvt4_kernel<<<dim3((D_ * H_ + 255) / 256, 4), 256>>>(Wq, Wk, Wv, Wo, wq, wk, wv, wo);

    ln1_kernel<<<ROWS, 256>>>(tokens, g1, b1, x);

    // fused QKV projection -> bf16 (wmma v3, 3-stage)
    cudaFuncSetAttribute(gemm_kernel<__nv_bfloat16>,
                         cudaFuncAttributeMaxDynamicSharedMemorySize, (int)GEMM_SMEM);
    gemm_kernel<__nv_bfloat16><<<dim3(H_ / GBN, ROWS / GBM, 3), GTHREADS, GEMM_SMEM>>>(
        x, wq, wk, wv, Qb, Kb, Vb);

    // sparse attention (warp-autonomous tensor-core)
    cudaFuncSetAttribute(attn_kernel, cudaFuncAttributeMaxDynamicSharedMemorySize,
                         (int)ATTN_SMEM);
    attn_kernel<<<dim3(S_ / QT, B_), ATHREADS, ATTN_SMEM>>>(Qb, Kb, Vb, attn);

    // output projection -> bf16 (wmma v3, 3-stage)
    gemm_kernel<__nv_bfloat16><<<dim3(D_ / GBN, ROWS / GBM, 1), GTHREADS, GEMM_SMEM>>>(
        attn, wo, wo, wo, ob, ob, ob);

    // residual + LN2
    ln2_kernel<<<ROWS, 256>>>(tokens, ob, g2, b2, out);
}

// round 17
// speedup vs baseline: 1.0947x; 1.0394x over previous
#include <cuda_runtime.h>
#include <cuda_bf16.h>
#include <mma.h>
#include <math.h>
#include <cstdint>

using namespace nvcuda;

// ---------------- problem constants ----------------
constexpr int B_   = 4;
constexpr int S_   = 4096;
constexpr int D_   = 1024;   // token dim
constexpr int H_   = 1024;   // hidden dim
constexpr int WIN  = 256;
constexpr int STRIDE_ = 128;
constexpr int GLOB = 16;
constexpr float EPS = 1e-5f;
constexpr float SCALE = 1.0f / 32.0f;  // 1/sqrt(1024)

constexpr int ROWS = B_ * S_;          // 16384
constexpr size_t NELEM = (size_t)ROWS * D_;  // 16,777,216

// ---------------- scratch (static device globals; allocation-free) ----------
__device__ __nv_bfloat16 g_x[NELEM];       // LN1 output (bf16)
__device__ __nv_bfloat16 g_wq[D_ * H_];
__device__ __nv_bfloat16 g_wk[D_ * H_];
__device__ __nv_bfloat16 g_wv[D_ * D_];
__device__ __nv_bfloat16 g_wo[D_ * D_];
__device__ __nv_bfloat16 g_Q[NELEM];
__device__ __nv_bfloat16 g_K[NELEM];
__device__ __nv_bfloat16 g_V[NELEM];
__device__ __nv_bfloat16 g_attn[NELEM];    // attention output (bf16)
__device__ __nv_bfloat16 g_o[NELEM];       // attn @ Wo (bf16)

// ---------------- cp.async helpers ----------------
__device__ __forceinline__ void cp16(void* sdst, const void* gsrc) {
    unsigned sa = (unsigned)__cvta_generic_to_shared(sdst);
    asm volatile("cp.async.cg.shared.global [%0], [%1], 16;\n" :: "r"(sa), "l"(gsrc));
}
#define CP_COMMIT() asm volatile("cp.async.commit_group;\n" ::: "memory")
#define CP_WAIT1()  asm volatile("cp.async.wait_group 1;\n" ::: "memory")

// ---------------- small bf16 vector helpers ----------------
__device__ __forceinline__ float dot8(uint4 u, const float* qv) {
    const __nv_bfloat162* h = (const __nv_bfloat162*)&u;
    float p = 0.f;
#pragma unroll
    for (int k = 0; k < 4; k++) {
        float2 t = __bfloat1622float2(h[k]);
        p += qv[2 * k] * t.x + qv[2 * k + 1] * t.y;
    }
    return p;
}
__device__ __forceinline__ void fma8(uint4 u, float w, float* acc) {
    const __nv_bfloat162* h = (const __nv_bfloat162*)&u;
#pragma unroll
    for (int k = 0; k < 4; k++) {
        float2 t = __bfloat1622float2(h[k]);
        acc[2 * k]     += w * t.x;
        acc[2 * k + 1] += w * t.y;
    }
}
__device__ __forceinline__ void unp8(uint4 u, float* f) {
    const __nv_bfloat162* h = (const __nv_bfloat162*)&u;
#pragma unroll
    for (int k = 0; k < 4; k++) {
        float2 t = __bfloat1622float2(h[k]);
        f[2 * k] = t.x; f[2 * k + 1] = t.y;
    }
}
__device__ __forceinline__ uint4 pack8(const float* a) {
    uint4 u;
    __nv_bfloat162* h = (__nv_bfloat162*)&u;
#pragma unroll
    for (int k = 0; k < 4; k++)
        h[k] = __floats2bfloat162_rn(a[2 * k], a[2 * k + 1]);
    return u;
}

// ---------------- weight conversion (all 4 weights, 1 launch) --------------
__global__ void cvt4_kernel(const float* __restrict__ w0, const float* __restrict__ w1,
                            const float* __restrict__ w2, const float* __restrict__ w3,
                            __nv_bfloat16* __restrict__ o0, __nv_bfloat16* __restrict__ o1,
                            __nv_bfloat16* __restrict__ o2, __nv_bfloat16* __restrict__ o3) {
    const float* w = (blockIdx.y == 0) ? w0 : (blockIdx.y == 1) ? w1 : (blockIdx.y == 2) ? w2 : w3;
    __nv_bfloat16* o = (blockIdx.y == 0) ? o0 : (blockIdx.y == 1) ? o1 : (blockIdx.y == 2) ? o2 : o3;
    int i = blockIdx.x * blockDim.x + threadIdx.x;
    if (i < D_ * H_) o[i] = __float2bfloat16(w[i]);
}

// ---------------- LayerNorm 1: warp-shuffle reduction, float4 --------------
__global__ void ln1_kernel(const float* __restrict__ tokens,
                           const float* __restrict__ g, const float* __restrict__ beta,
                           __nv_bfloat16* __restrict__ out) {
    int row = blockIdx.x, tid = threadIdx.x, lane = tid & 31, wid = tid >> 5;
    float4 v = ((const float4*)(tokens + (size_t)row * D_))[tid];
    float s  = v.x + v.y + v.z + v.w;
    float ss = v.x * v.x + v.y * v.y + v.z * v.z + v.w * v.w;
#pragma unroll
    for (int o = 16; o > 0; o >>= 1) {
        s  += __shfl_xor_sync(0xffffffffu, s, o);
        ss += __shfl_xor_sync(0xffffffffu, ss, o);
    }
    __shared__ float as[8], bs[8];
    if (lane == 0) { as[wid] = s; bs[wid] = ss; }
    __syncthreads();
    if (tid < 32) {
        float a = (lane < 8) ? as[lane] : 0.f;
        float b = (lane < 8) ? bs[lane] : 0.f;
#pragma unroll
        for (int o = 4; o > 0; o >>= 1) {
            a += __shfl_xor_sync(0xffffffffu, a, o);
            b += __shfl_xor_sync(0xffffffffu, b, o);
        }
        if (lane == 0) { as[0] = a; bs[0] = b; }
    }
    __syncthreads();
    float mean = as[0] * (1.0f / D_);
    float var  = bs[0] * (1.0f / D_) - mean * mean;
    float inv  = rsqrtf(var + EPS);
    float4 gg = ((const float4*)g)[tid];
    float4 bb = ((const float4*)beta)[tid];
    float o0 = (v.x - mean) * inv * gg.x + bb.x;
    float o1 = (v.y - mean) * inv * gg.y + bb.y;
    float o2 = (v.z - mean) * inv * gg.z + bb.z;
    float o3 = (v.w - mean) * inv * gg.w + bb.w;
    uint2 pk;
    ((__nv_bfloat162*)&pk)[0] = __floats2bfloat162_rn(o0, o1);
    ((__nv_bfloat162*)&pk)[1] = __floats2bfloat162_rn(o2, o3);
    ((uint2*)(out + (size_t)row * D_))[tid] = pk;
}

// ---------------- LayerNorm 2: tokens + 0.1*o(bf16) -> fp32 out ------------
__global__ void ln2_kernel(const float* __restrict__ tokens,
                           const __nv_bfloat16* __restrict__ oin,
                           const float* __restrict__ g, const float* __restrict__ beta,
                           float* __restrict__ out) {
    int row = blockIdx.x, tid = threadIdx.x, lane = tid & 31, wid = tid >> 5;
    float4 v = ((const float4*)(tokens + (size_t)row * D_))[tid];
    uint2 ou = ((const uint2*)(oin + (size_t)row * D_))[tid];
    float2 oa = __bfloat1622float2(((const __nv_bfloat162*)&ou)[0]);
    float2 ob = __bfloat1622float2(((const __nv_bfloat162*)&ou)[1]);
    v.x += 0.1f * oa.x; v.y += 0.1f * oa.y;
    v.z += 0.1f * ob.x; v.w += 0.1f * ob.y;
    float s  = v.x + v.y + v.z + v.w;
    float ss = v.x * v.x + v.y * v.y + v.z * v.z + v.w * v.w;
#pragma unroll
    for (int o = 16; o > 0; o >>= 1) {
        s  += __shfl_xor_sync(0xffffffffu, s, o);
        ss += __shfl_xor_sync(0xffffffffu, ss, o);
    }
    __shared__ float as[8], bs[8];
    if (lane == 0) { as[wid] = s; bs[wid] = ss; }
    __syncthreads();
    if (tid < 32) {
        float a = (lane < 8) ? as[lane] : 0.f;
        float b = (lane < 8) ? bs[lane] : 0.f;
#pragma unroll
        for (int o = 4; o > 0; o >>= 1) {
            a += __shfl_xor_sync(0xffffffffu, a, o);
            b += __shfl_xor_sync(0xffffffffu, b, o);
        }
        if (lane == 0) { as[0] = a; bs[0] = b; }
    }
    __syncthreads();
    float mean = as[0] * (1.0f / D_);
    float var  = bs[0] * (1.0f / D_) - mean * mean;
    float inv  = rsqrtf(var + EPS);
    float4 gg = ((const float4*)g)[tid];
    float4 bb = ((const float4*)beta)[tid];
    float4 r;
    r.x = (v.x - mean) * inv * gg.x + bb.x;
    r.y = (v.y - mean) * inv * gg.y + bb.y;
    r.z = (v.z - mean) * inv * gg.z + bb.z;
    r.w = (v.w - mean) * inv * gg.w + bb.w;
    ((float4*)(out + (size_t)row * D_))[tid] = r;
}

// ---------------- wmma bf16 GEMM v3: 128x128x64, 3-stage, 1 sync/iter ------
constexpr int GBM = 128, GBN = 128, GBK = 64;
constexpr int ALD = 72;
constexpr int BLD = 136;
constexpr int GTHREADS = 256;
constexpr int GSTAGES = 3;
constexpr int ABUF = GBM * ALD;
constexpr int BBUF = GBK * BLD;
constexpr size_t GEMM_SMEM = (size_t)GSTAGES * (ABUF + BBUF) * 2;
constexpr int GNKC = D_ / GBK;

template <typename OT>
__global__ __launch_bounds__(GTHREADS, 2)
void gemm_kernel(const __nv_bfloat16* __restrict__ A,
                 const __nv_bfloat16* __restrict__ B0,
                 const __nv_bfloat16* __restrict__ B1,
                 const __nv_bfloat16* __restrict__ B2,
                 OT* __restrict__ C0, OT* __restrict__ C1, OT* __restrict__ C2) {
    const __nv_bfloat16* Bm = (blockIdx.z == 0) ? B0 : (blockIdx.z == 1) ? B1 : B2;
    OT* C = (blockIdx.z == 0) ? C0 : (blockIdx.z == 1) ? C1 : C2;

    extern __shared__ __align__(16) __nv_bfloat16 gsm[];
    __nv_bfloat16* As = gsm;
    __nv_bfloat16* Bs = gsm + GSTAGES * ABUF;

    int m0 = blockIdx.y * GBM;
    int n0 = blockIdx.x * GBN;
    int tid = threadIdx.x;
    int lane = tid & 31;
    int wid = tid >> 5;
    int wm = wid & 3;
    int wn = wid >> 2;

    wmma::fragment<wmma::accumulator, 16, 16, 16, float> cf[2][4];
#pragma unroll
    for (int r = 0; r < 2; r++)
#pragma unroll
        for (int c = 0; c < 4; c++)
            wmma::fill_fragment(cf[r][c], 0.0f);

    auto issue = [&](int s, int k0) {
        __nv_bfloat16* Ab = As + s * ABUF;
        __nv_bfloat16* Bb = Bs + s * BBUF;
#pragma unroll
        for (int it = 0; it < 4; it++) {
            int idx = tid + it * GTHREADS;
            int row = idx >> 3, c8 = idx & 7;
            cp16(&Ab[row * ALD + c8 * 8],
                 &A[(size_t)(m0 + row) * 1024 + k0 + c8 * 8]);
        }
#pragma unroll
        for (int it = 0; it < 4; it++) {
            int idx = tid + it * GTHREADS;
            int row = idx >> 4, c16 = idx & 15;
            cp16(&Bb[row * BLD + c16 * 8],
                 &Bm[(size_t)(k0 + row) * 1024 + n0 + c16 * 8]);
        }
    };

    issue(0, 0);
    CP_COMMIT();
    issue(1, GBK);
    CP_COMMIT();

    for (int kt = 0; kt < GNKC; kt++) {
        CP_WAIT1();
        __syncthreads();
        if (kt + 2 < GNKC) issue((kt + 2) % GSTAGES, (kt + 2) * GBK);
        CP_COMMIT();

        int s = kt % GSTAGES;
        __nv_bfloat16* Ab = As + s * ABUF;
        __nv_bfloat16* Bb = Bs + s * BBUF;
#pragma unroll
        for (int kk = 0; kk < 4; kk++) {
            wmma::fragment<wmma::matrix_a, 16, 16, 16, __nv_bfloat16, wmma::row_major> af[2];
            wmma::fragment<wmma::matrix_b, 16, 16, 16, __nv_bfloat16, wmma::row_major> bf[4];
#pragma unroll
            for (int r = 0; r < 2; r++)
                wmma::load_matrix_sync(af[r], Ab + (wm * 32 + r * 16) * ALD + kk * 16, ALD);
#pragma unroll
            for (int c = 0; c < 4; c++)
                wmma::load_matrix_sync(bf[c], Bb + (kk * 16) * BLD + wn * 64 + c * 16, BLD);
#pragma unroll
            for (int r = 0; r < 2; r++)
#pragma unroll
                for (int c = 0; c < 4; c++)
                    wmma::mma_sync(cf[r][c], af[r], bf[c], cf[r][c]);
        }
    }
    __syncthreads();

    if constexpr (sizeof(OT) == 4) {
#pragma unroll
        for (int r = 0; r < 2; r++)
#pragma unroll
            for (int c = 0; c < 4; c++) {
                float* p = (float*)C + (size_t)(m0 + wm * 32 + r * 16) * 1024
                           + n0 + wn * 64 + c * 16;
                wmma::store_matrix_sync(p, cf[r][c], 1024, wmma::mem_row_major);
            }
    } else {
        float* my = (float*)gsm + wid * 256;
#pragma unroll
        for (int r = 0; r < 2; r++)
#pragma unroll
            for (int c = 0; c < 4; c++) {
                wmma::store_matrix_sync(my, cf[r][c], 16, wmma::mem_row_major);
                __syncwarp();
                int r2 = lane >> 1;
                int cb = (lane & 1) * 8;
                __nv_bfloat16 pk[8];
#pragma unroll
                for (int e = 0; e < 8; e++)
                    pk[e] = __float2bfloat16(my[r2 * 16 + cb + e]);
                __nv_bfloat16* p = (__nv_bfloat16*)C
                    + (size_t)(m0 + wm * 32 + r * 16 + r2) * 1024
                    + n0 + wn * 64 + c * 16 + cb;
                *(uint4*)p = *(uint4*)pk;
                __syncwarp();
            }
    }
}

// ---------------- sparse attention v4: tensor window + scalar strided ------
// klist = window-union + global keys only (<=303). Strided pairs (one key per
// query, j ≡ i mod 128, j < wstart) handled by a scalar path: warp w = query
// w does ~30 direct 1024-dot scores from L2 and ~30 weighted V-row register
// accumulations, parked as a bf16 row in the warp's own K buffer; tensor-AV
// epilogue adds it on the way out. 4 block barriers total.
constexpr int QT = 16;
constexpr int MAXU = 320;
constexpr int ATHREADS = 512;
constexpr int LDQ  = 1032;
constexpr int LDK  = 72;
constexpr int LDSC = 320;
constexpr int LDW  = 328;
constexpr int SMAX = 32;
constexpr int WBUF = 16 * LDK;     // 1152 elems

constexpr size_t ATTN_SMEM =
    (size_t)QT * LDQ * 2           // Qs
  + (size_t)16 * 2 * WBUF * 2      // per-warp K/V double buffers / ssout rows
  + (size_t)QT * LDW * 2           // scb (bf16 weights)
  + (size_t)QT * LDSC * 4          // sc (fp32 scores)
  + (size_t)QT * SMAX * 4          // ss (strided raw scores)
  + (size_t)QT * SMAX * 4          // sw (strided weights)
  + (size_t)MAXU * 4 + 16;         // klist + cnt

__global__ __launch_bounds__(ATHREADS, 1)
void attn_kernel(const __nv_bfloat16* __restrict__ Q,
                 const __nv_bfloat16* __restrict__ K,
                 const __nv_bfloat16* __restrict__ V,
                 __nv_bfloat16* __restrict__ attn) {
    extern __shared__ char smem_raw[];
    __nv_bfloat16* Qs  = (__nv_bfloat16*)smem_raw;            // [QT][LDQ]
    __nv_bfloat16* Kb  = Qs + QT * LDQ;                       // [16][2][WBUF]
    __nv_bfloat16* scb = Kb + 16 * 2 * WBUF;                  // [QT][LDW]
    float*         sc  = (float*)(scb + QT * LDW);            // [QT][LDSC]
    float*         ss  = sc + QT * LDSC;                      // [QT][SMAX]
    float*         sw  = ss + QT * SMAX;                      // [QT][SMAX]
    int*         klist = (int*)(sw + QT * SMAX);              // [MAXU]
    int*          cntp = klist + MAXU;

    int b    = blockIdx.y;
    int i0   = (gridDim.x - 1 - blockIdx.x) * QT;   // heaviest tiles first
    int tid  = threadIdx.x;
    int lane = tid & 31;
    int wid  = tid >> 5;

    // ---- stage Q tile ----
    const __nv_bfloat16* Qbase = Q + ((size_t)b * S_ + i0) * H_;
#pragma unroll
    for (int it = 0; it < 4; it++) {
        int id = tid + it * ATHREADS;
        int row = id >> 7, seg = id & 127;
        *(uint4*)&Qs[row * LDQ + seg * 8] = *(const uint4*)&Qbase[row * 1024 + seg * 8];
    }

    // ---- klist: window-union + global only (ballot scan, ascending) ----
    int imax   = i0 + QT - 1;
    int wstart = max(0, i0 - (WIN - 1));
    if (wid == 0) {
        int c = 0;
        for (int j0 = 0; j0 <= imax; j0 += 32) {
            int j = j0 + lane;
            bool inc = (j <= imax) && ((j >= wstart) || (j < GLOB));
            unsigned msk = __ballot_sync(0xffffffffu, inc);
            if (inc) klist[c + __popc(msk & ((1u << lane) - 1u))] = j;
            c += __popc(msk);
        }
        if (lane == 0) *cntp = c;
        for (int k = c + lane; k < MAXU; k += 32) klist[k] = 0;
    }
    __syncthreads();                                   // barrier #1
    int wcnt = *cntp;
    int ntiles = (wcnt + 15) >> 4;

    __nv_bfloat16* Kw = Kb + wid * 2 * WBUF;
    const __nv_bfloat16* Kbase = K + (size_t)b * S_ * H_;
    const __nv_bfloat16* Vbase = V + (size_t)b * S_ * H_;

    // ---- strided setup for this warp's query (warp w <-> query w) ----
    int iq = i0 + wid;
    int rr = iq & 127;
    int num = wstart - 1 - rr;
    int t1 = (num >= 0) ? (num >> 7) : -1;
    int tmin = (rr >= GLOB) ? 0 : 1;
    int nm = t1 - tmin + 1;
    if (nm < 0) nm = 0;
    if (nm > SMAX) nm = SMAX;
    int j1 = rr + (t1 << 7);

    // lane-private Q slice for scalar dots (elems blk*256 + lane*8 + e)
    float qv[32];
    {
        const uint4* Qr4 = (const uint4*)(Qs + wid * LDQ);
#pragma unroll
        for (int blk = 0; blk < 4; blk++)
            unp8(Qr4[blk * 32 + lane], qv + blk * 8);
    }

    // ---- score phase ----
    {
        int nmy = 0;
        for (int kt = wid; kt < ntiles; kt += 16) nmy++;
        int tslabs = nmy * 16;

        auto issueK = [&](int it) {
            int buf = it & 1;
            int kt  = wid + ((it >> 4) << 4);
            int k0  = (it & 15) * 64;
#pragma unroll
            for (int l = 0; l < 4; l++) {
                int id = lane + 32 * l;
                int row = id >> 3, seg = id & 7;
                int j = klist[kt * 16 + row];
                cp16(&Kw[buf * WBUF + row * LDK + seg * 8],
                     Kbase + (size_t)j * 1024 + k0 + seg * 8);
            }
        };

        if (tslabs > 0) { issueK(0); }
        CP_COMMIT();

        // scalar strided scores (overlaps first K slab in flight)
        for (int m = 0; m < nm; m++) {
            int j = j1 - (m << 7);
            const uint4* Kr4 = (const uint4*)(Kbase + (size_t)j * 1024);
            float p = 0.f;
#pragma unroll
            for (int blk = 0; blk < 4; blk++)
                p += dot8(Kr4[blk * 32 + lane], qv + blk * 8);
#pragma unroll
            for (int o = 16; o > 0; o >>= 1) p += __shfl_down_sync(0xffffffffu, p, o);
            if (lane == 0) ss[wid * SMAX + m] = p;
        }

        // tensor window/global scores
        wmma::fragment<wmma::accumulator, 16, 16, 16, float> sf;
        wmma::fill_fragment(sf, 0.0f);
        for (int it = 0; it < tslabs; it++) {
            if (it + 1 < tslabs) issueK(it + 1);
            CP_COMMIT();
            CP_WAIT1();
            __syncwarp();
            int buf = it & 1;
            int k0  = (it & 15) * 64;
#pragma unroll
            for (int i = 0; i < 4; i++) {
                wmma::fragment<wmma::matrix_a, 16, 16, 16, __nv_bfloat16, wmma::row_major> af;
                wmma::fragment<wmma::matrix_b, 16, 16, 16, __nv_bfloat16, wmma::col_major> bf;
                wmma::load_matrix_sync(af, Qs + k0 + i * 16, LDQ);
                wmma::load_matrix_sync(bf, Kw + buf * WBUF + i * 16, LDK);
                wmma::mma_sync(sf, af, bf, sf);
            }
            if ((it & 15) == 15) {
                int kt = wid + ((it >> 4) << 4);
                wmma::store_matrix_sync(sc + kt * 16, sf, LDSC, wmma::mem_row_major);
                wmma::fill_fragment(sf, 0.0f);
            }
        }
    }
    __syncthreads();                                   // barrier #2

    // ---- mask + softmax over klist scores + strided scores ----
    int cnt16 = ntiles << 4;
    {
        int q = wid;
        int i = i0 + q;
        float mx = -INFINITY;
        for (int ku = lane; ku < wcnt; ku += 32) {
            int j = klist[ku];
            int d = i - j;
            bool ok = (d >= 0) && ((d < WIN) || ((d & (STRIDE_ - 1)) == 0) || (j < GLOB));
            float v = ok ? sc[q * LDSC + ku] * SCALE : -INFINITY;
            sc[q * LDSC + ku] = v;
            mx = fmaxf(mx, v);
        }
        if (lane < nm) mx = fmaxf(mx, ss[q * SMAX + lane] * SCALE);
#pragma unroll
        for (int o = 16; o > 0; o >>= 1) mx = fmaxf(mx, __shfl_xor_sync(0xffffffffu, mx, o));
        float ssum = 0.f;
        for (int ku = lane; ku < wcnt; ku += 32) {
            float e = __expf(sc[q * LDSC + ku] - mx);
            sc[q * LDSC + ku] = e;
            ssum += e;
        }
        if (lane < nm) {
            float e = __expf(ss[q * SMAX + lane] * SCALE - mx);
            sw[q * SMAX + lane] = e;
            ssum += e;
        }
#pragma unroll
        for (int o = 16; o > 0; o >>= 1) ssum += __shfl_xor_sync(0xffffffffu, ssum, o);
        float inv = 1.f / ssum;
        for (int ku = lane; ku < cnt16; ku += 32) {
            float w = (ku < wcnt) ? sc[q * LDSC + ku] * inv : 0.f;
            scb[q * LDW + ku] = __float2bfloat16(w);
        }
        if (lane < nm) sw[q * SMAX + lane] *= inv;
    }
    __syncthreads();                                   // barrier #3

    // ---- AV phase: tensor over klist + scalar strided ----
    int d0 = wid * 64;
    wmma::fragment<wmma::accumulator, 16, 16, 16, float> of[4];
#pragma unroll
    for (int i = 0; i < 4; i++) wmma::fill_fragment(of[i], 0.0f);
    {
        auto issueV = [&](int c) {
            int buf = c & 1;
#pragma unroll
            for (int l = 0; l < 4; l++) {
                int id = lane + 32 * l;
                int row = id >> 3, seg = id & 7;
                int j = klist[c * 16 + row];
                cp16(&Kw[buf * WBUF + row * LDK + seg * 8],
                     Vbase + (size_t)j * 1024 + d0 + seg * 8);
            }
        };

        issueV(0);
        CP_COMMIT();
        for (int c = 0; c < ntiles; c++) {
            if (c + 1 < ntiles) issueV(c + 1);
            CP_COMMIT();
            CP_WAIT1();
            __syncwarp();
            int buf = c & 1;
            wmma::fragment<wmma::matrix_a, 16, 16, 16, __nv_bfloat16, wmma::row_major> af;
            wmma::load_matrix_sync(af, scb + c * 16, LDW);
#pragma unroll
            for (int i = 0; i < 4; i++) {
                wmma::fragment<wmma::matrix_b, 16, 16, 16, __nv_bfloat16, wmma::row_major> bf;
                wmma::load_matrix_sync(bf, Kw + buf * WBUF + i * 16, LDK);
                wmma::mma_sync(of[i], af, bf, of[i]);
            }
        }
    }

    // scalar strided AV: full 1024-wide row for this warp's query, in regs,
    // parked as bf16 row in this warp's own (now free) K buffer region.
    {
        float acc[32];
#pragma unroll
        for (int e = 0; e < 32; e++) acc[e] = 0.f;
        for (int m = 0; m < nm; m++) {
            int j = j1 - (m << 7);
            float wm = sw[wid * SMAX + m];
            const uint4* Vr4 = (const uint4*)(Vbase + (size_t)j * 1024);
#pragma unroll
            for (int blk = 0; blk < 4; blk++)
                fma8(Vr4[blk * 32 + lane], wm, acc + blk * 8);
        }
        __nv_bfloat16* so = Kb + wid * 2 * WBUF;   // ssout row (2048 <= 2304)
#pragma unroll
        for (int blk = 0; blk < 4; blk++)
            *(uint4*)&so[blk * 256 + lane * 8] = pack8(acc + blk * 8);
    }
    __syncthreads();                                   // barrier #4

    // ---- epilogue: tensor frags + ssout rows -> bf16 gmem ----
    {
        float* my = sc + wid * 256;
#pragma unroll
        for (int i = 0; i < 4; i++) {
            wmma::store_matrix_sync(my, of[i], 16, wmma::mem_row_major);
            __syncwarp();
            int r2 = lane >> 1, cb = (lane & 1) * 8;
            const __nv_bfloat16* so = Kb + r2 * 2 * WBUF;
            uint4 sv = *(const uint4*)&so[d0 + i * 16 + cb];
            float sf8[8];
            unp8(sv, sf8);
            __nv_bfloat16 pk[8];
#pragma unroll
            for (int e = 0; e < 8; e++)
                pk[e] = __float2bfloat16(my[r2 * 16 + cb + e] + sf8[e]);
            *(uint4*)(attn + ((size_t)b * S_ + i0 + r2) * 1024 + d0 + i * 16 + cb) = *(uint4*)pk;
            __syncwarp();
        }
    }
}

// ---------------- launch ----------------
extern "C" void kernel_launch(void* const* d_in, const int* in_sizes, int n_in,
                              void* d_out, int out_size) {
    const float* tokens = (const float*)d_in[0];
    const float* Wq = (const float*)d_in[1];
    const float* Wk = (const float*)d_in[2];
    const float* Wv = (const float*)d_in[3];
    const float* Wo = (const float*)d_in[4];
    const float* g1 = (const float*)d_in[5];
    const float* b1 = (const float*)d_in[6];
    const float* g2 = (const float*)d_in[7];
    const float* b2 = (const float*)d_in[8];
    float* out = (float*)d_out;

    __nv_bfloat16 *x, *wq, *wk, *wv, *wo, *Qb, *Kb, *Vb, *attn, *ob;
    cudaGetSymbolAddress((void**)&x,    g_x);
    cudaGetSymbolAddress((void**)&wq,   g_wq);
    cudaGetSymbolAddress((void**)&wk,   g_wk);
    cudaGetSymbolAddress((void**)&wv,   g_wv);
    cudaGetSymbolAddress((void**)&wo,   g_wo);
    cudaGetSymbolAddress((void**)&Qb,   g_Q);
    cudaGetSymbolAddress((void**)&Kb,   g_K);
    cudaGetSymbolAddress((void**)&Vb,   g_V);
    cudaGetSymbolAddress((void**)&attn, g_attn);
    cudaGetSymbolAddress((void**)&ob,   g_o);

    cvt4_kernel<<<dim3((D_ * H_ + 255) / 256, 4), 256>>>(Wq, Wk, Wv, Wo, wq, wk, wv, wo);

    ln1_kernel<<<ROWS, 256>>>(tokens, g1, b1, x);

    // fused QKV projection -> bf16 (wmma v3, 3-stage)
    cudaFuncSetAttribute(gemm_kernel<__nv_bfloat16>,
                         cudaFuncAttributeMaxDynamicSharedMemorySize, (int)GEMM_SMEM);
    gemm_kernel<__nv_bfloat16><<<dim3(H_ / GBN, ROWS / GBM, 3), GTHREADS, GEMM_SMEM>>>(
        x, wq, wk, wv, Qb, Kb, Vb);

    // sparse attention v4 (tensor window + scalar strided)
    cudaFuncSetAttribute(attn_kernel, cudaFuncAttributeMaxDynamicSharedMemorySize,
                         (int)ATTN_SMEM);
    attn_kernel<<<dim3(S_ / QT, B_), ATHREADS, ATTN_SMEM>>>(Qb, Kb, Vb, attn);

    // output projection -> bf16 (wmma v3, 3-stage)
    gemm_kernel<__nv_bfloat16><<<dim3(D_ / GBN, ROWS / GBM, 1), GTHREADS, GEMM_SMEM>>>(
        attn, wo, wo, wo, ob, ob, ob);

    // residual + LN2
    ln2_kernel<<<ROWS, 256>>>(tokens, ob, g2, b2, out);
}